// round 7
// baseline (speedup 1.0000x reference)
#include <cuda_runtime.h>
#include <cstdint>

// Single fused kernel.
// out[o*256+k][h][m] = sum_{i,j} w[i][k][j] * xp[m+j], xp = padded/rolled row.
// Grid = 112 blocks (okt:4, h:14, mh:2). Block = 1024 thr = 8 i-groups x 128 k.
// Each group accumulates 32 i's (8 chunks of 4 il, weights cp.async
// double-buffered); cross-group reduction in smem, fixed order (deterministic).

#define CHUNKS    8
#define GROUPS    8
#define IL_PER_CH 4
#define ROWS_PER_CH (GROUPS * IL_PER_CH)          // 32
#define SW_FLOATS (ROWS_PER_CH * 384)             // 12288 floats = 48KB
#define SXE_OFF  (2 * SW_FLOATS)                  // sxe (256 x 16)
#define SXO_OFF  (SXE_OFF + 4096)                 // sxo (256 x 16)
#define SMEM_BYTES ((2 * SW_FLOATS + 4096 + 4096) * 4)   // 128 KB

extern __shared__ float smem[];

__device__ __forceinline__ uint64_t pk2(float v) {
    uint64_t r;
    asm("mov.b64 %0, {%1, %1};" : "=l"(r) : "r"(__float_as_uint(v)));
    return r;
}
__device__ __forceinline__ uint64_t ffma2(uint64_t a, uint64_t b, uint64_t c) {
    uint64_t d;
    asm("fma.rn.f32x2 %0, %1, %2, %3;" : "=l"(d) : "l"(a), "l"(b), "l"(c));
    return d;
}
__device__ __forceinline__ void cp16(uint32_t s, const void* g) {
    asm volatile("cp.async.cg.shared.global [%0], [%1], 16;" :: "r"(s), "l"(g) : "memory");
}
__device__ __forceinline__ void cp_commit() {
    asm volatile("cp.async.commit_group;" ::: "memory");
}
template <int N> __device__ __forceinline__ void cp_wait() {
    asm volatile("cp.async.wait_group %0;" :: "n"(N) : "memory");
}

__global__ __launch_bounds__(1024, 1)
void fused_conv_kernel(const float* __restrict__ x,
                       const float* __restrict__ w,
                       float* __restrict__ out) {
    const int okt = blockIdx.x / 28;
    const int rem = blockIdx.x % 28;
    const int h   = rem >> 1;
    const int mh  = rem & 1;           // m-half
    const int o   = okt >> 1;
    const int kt  = okt & 1;
    const int tid = threadIdx.x;
    const int g   = tid >> 7;          // i-group 0..7
    const int tx  = tid & 127;         // k within tile
    const int n   = (h + 13) % 14;     // undo roll along H

    const uint32_t sw_u32 = (uint32_t)__cvta_generic_to_shared(smem);

    // chunk c, buffer row r (0..31): i = (r>>2)*32 + c*4 + (r&3)
    // each row = 384 contiguous floats (kt half of w row i). 3072 f4/chunk.
    const float* wb = w + (size_t)kt * 384;
#pragma unroll
    for (int c0 = 0; c0 < 2; c0++) {
#pragma unroll
        for (int it = 0; it < 3; it++) {
            const int f4 = it * 1024 + tid;
            const int r = f4 / 96;
            const int within = f4 % 96;
            const int i = (r >> 2) * 32 + c0 * IL_PER_CH + (r & 3);
            cp16(sw_u32 + (uint32_t)(c0 * SW_FLOATS + r * 384 + within * 4) * 4,
                 wb + (size_t)i * 768 + within * 4);
        }
        cp_commit();
    }

    // ---- stage x rows, pre-shifted by 6*mh so operand pairs are aligned ----
    // sxe[i][mm] = xp[mm + 6*mh], sxo[i][mm] = xp[mm + 1 + 6*mh]
    // xp[a] = (a in [1,14]) ? x[o*256+i][n][(a+12)%14] : 0
    {
        const float* xbase = x + ((size_t)o * 256) * 196 + n * 14;
        const int sh = 6 * mh;
#pragma unroll
        for (int rep = 0; rep < 4; rep++) {
            const int idx = rep * 1024 + tid;      // 0..4095
            const int i = idx >> 4;
            const int mm = idx & 15;
            const int a = mm + sh;
            const int b = a + 1;
            float ve = 0.f, vo = 0.f;
            if (a >= 1 && a <= 14) ve = xbase[(size_t)i * 196 + (a + 12) % 14];
            if (b <= 14)           vo = xbase[(size_t)i * 196 + (b + 12) % 14];
            smem[SXE_OFF + idx] = ve;
            smem[SXO_OFF + idx] = vo;
        }
    }

    uint64_t A[4];
#pragma unroll
    for (int p = 0; p < 4; p++) A[p] = 0ull;

    // ---- main loop over 8 chunks, double-buffered ----
    for (int c = 0; c < CHUNKS; c++) {
        if (c == CHUNKS - 1) cp_wait<0>(); else cp_wait<1>();
        __syncthreads();                       // chunk c visible (+ x staging on c=0)

        const int buf = c & 1;
        const float* swp = smem + buf * SW_FLOATS + (g * IL_PER_CH) * 384 + tx * 3;
        const float* xe  = smem + SXE_OFF + (size_t)(g * 32 + c * IL_PER_CH) * 16;
        const float* xo  = smem + SXO_OFF + (size_t)(g * 32 + c * IL_PER_CH) * 16;

#pragma unroll
        for (int il = 0; il < IL_PER_CH; il++) {
            const uint64_t W0 = pk2(swp[il * 384 + 0]);
            const uint64_t W1 = pk2(swp[il * 384 + 1]);
            const uint64_t W2 = pk2(swp[il * 384 + 2]);

            const ulonglong2 e01 = *(const ulonglong2*)(xe + il * 16);
            const ulonglong2 e23 = *(const ulonglong2*)(xe + il * 16 + 4);
            const uint64_t   e4  = *(const uint64_t*)  (xe + il * 16 + 8);
            const ulonglong2 o01 = *(const ulonglong2*)(xo + il * 16);
            const ulonglong2 o23 = *(const ulonglong2*)(xo + il * 16 + 4);

            uint64_t E[5] = {e01.x, e01.y, e23.x, e23.y, e4};
            uint64_t O[4] = {o01.x, o01.y, o23.x, o23.y};

#pragma unroll
            for (int p = 0; p < 4; p++) {
                A[p] = ffma2(W0, E[p],     A[p]);
                A[p] = ffma2(W1, O[p],     A[p]);
                A[p] = ffma2(W2, E[p + 1], A[p]);
            }
        }
        __syncthreads();                       // done reading buf before refill
        if (c + 2 < CHUNKS) {
#pragma unroll
            for (int it = 0; it < 3; it++) {
                const int f4 = it * 1024 + tid;
                const int r = f4 / 96;
                const int within = f4 % 96;
                const int i = (r >> 2) * 32 + (c + 2) * IL_PER_CH + (r & 3);
                cp16(sw_u32 + (uint32_t)(buf * SW_FLOATS + r * 384 + within * 4) * 4,
                     wb + (size_t)i * 768 + within * 4);
            }
            cp_commit();
        }
    }

    // ---- cross-group reduction in smem (reuse weight buffers) ----
    // ps[(g*128 + k)*4 + p] : float2 partial for pair p
    uint64_t* ps = (uint64_t*)smem;
#pragma unroll
    for (int p = 0; p < 4; p++)
        ps[((size_t)(g * 128 + tx) << 2) + p] = A[p];
    __syncthreads();

    if (tid < 512) {
        const int k = tid >> 2;                // 0..127
        const int p = tid & 3;
        float vlo = 0.f, vhi = 0.f;
#pragma unroll
        for (int gg = 0; gg < GROUPS; gg++) {  // fixed order -> deterministic
            const float2 v = ((const float2*)ps)[((gg * 128 + k) << 2) + p];
            vlo += v.x;
            vhi += v.y;
        }

        const int cg   = o * 256 + kt * 128 + k;
        const int base = cg * 196 + h * 14;
        const int m0   = 6 * mh + 2 * p;
        if (mh == 0) {
            if (p < 3) { out[base + m0] = vlo; out[base + m0 + 1] = vhi; }
            else       { out[base + 6] = vlo; }
        } else {
            if (p == 0) { out[base + 7] = vhi; }
            else        { out[base + m0] = vlo; out[base + m0 + 1] = vhi; }
        }
    }
}

extern "C" void kernel_launch(void* const* d_in, const int* in_sizes, int n_in,
                              void* d_out, int out_size) {
    const float* x = (const float*)d_in[0];   // (1,512,14,14)
    const float* w = (const float*)d_in[1];   // (256,256,3)
    float* out = (float*)d_out;

    cudaFuncSetAttribute(fused_conv_kernel,
                         cudaFuncAttributeMaxDynamicSharedMemorySize, SMEM_BYTES);
    fused_conv_kernel<<<112, 1024, SMEM_BYTES>>>(x, w, out);
}

// round 8
// speedup vs baseline: 1.2924x; 1.2924x over previous
#include <cuda_runtime.h>
#include <cstdint>

// Single fused kernel.
// out[o*256+k][h][m] = sum_{i,j} w[i][k][j] * xp[m+j], xp = padded/rolled row.
// Grid = 112 blocks (o:2, kq:4, h:14). Block = 512 thr = 8 i-groups x 64 k.
// Thread: one k, all 14 m as 7 f32x2 accumulators, 32 i's (8 chunks x 4 il).
// Weights cp.async 3-deep pipelined (one barrier per chunk). Cross-group
// reduction in smem, fixed order (deterministic).

#define CHUNKS 8
#define NBUF   3
#define CHUNK_FLOATS (32 * 192)          // 32 rows x (64 k x 3 taps) = 24KB
#define SXE_OFF (NBUF * CHUNK_FLOATS)    // 256 x 16 floats
#define SXO_OFF (SXE_OFF + 4096)
#define SMEM_FLOATS (SXO_OFF + 4096)     // 26624 floats = 104KB
#define SMEM_BYTES (SMEM_FLOATS * 4)

extern __shared__ float smem[];

__device__ __forceinline__ uint64_t pk2(float v) {
    uint64_t r;
    asm("mov.b64 %0, {%1, %1};" : "=l"(r) : "r"(__float_as_uint(v)));
    return r;
}
__device__ __forceinline__ uint64_t ffma2(uint64_t a, uint64_t b, uint64_t c) {
    uint64_t d;
    asm("fma.rn.f32x2 %0, %1, %2, %3;" : "=l"(d) : "l"(a), "l"(b), "l"(c));
    return d;
}
__device__ __forceinline__ void cp16(uint32_t s, const void* g) {
    asm volatile("cp.async.cg.shared.global [%0], [%1], 16;" :: "r"(s), "l"(g) : "memory");
}
__device__ __forceinline__ void cp_commit() {
    asm volatile("cp.async.commit_group;" ::: "memory");
}
template <int N> __device__ __forceinline__ void cp_wait() {
    asm volatile("cp.async.wait_group %0;" :: "n"(N) : "memory");
}

__global__ __launch_bounds__(512, 1)
void fused_conv_kernel(const float* __restrict__ x,
                       const float* __restrict__ w,
                       float* __restrict__ out) {
    const int bx = blockIdx.x;          // 0..111
    const int o  = bx / 56;
    const int kq = (bx / 14) & 3;       // 64-k quarter
    const int h  = bx % 14;
    const int tid = threadIdx.x;
    const int g   = tid >> 6;           // i-group 0..7 (32 i each)
    const int tx  = tid & 63;           // k within quarter
    const int n   = (h + 13) % 14;      // undo roll along H

    const uint32_t s_u32 = (uint32_t)__cvta_generic_to_shared(smem);

    // ---- weight chunk copy: chunk c, buffer row r (0..31): i = (r>>2)*32 + c*4 + (r&3)
    // row = 192 contiguous floats: w[i][kq*64 .. +64][3] = w + i*768 + kq*192.
    const float* wb = w + (size_t)kq * 192;
#define ISSUE_CHUNK(cc, buf)                                                     \
    {                                                                            \
        _Pragma("unroll")                                                        \
        for (int it = 0; it < 3; it++) {                                         \
            const int f4 = it * 512 + tid;          /* 0..1535 */                \
            const int r = f4 / 48;                                               \
            const int within = f4 % 48;                                          \
            const int i = (r >> 2) * 32 + (cc) * 4 + (r & 3);                    \
            cp16(s_u32 + (uint32_t)((buf) * CHUNK_FLOATS + r * 192 + within * 4) * 4, \
                 wb + (size_t)i * 768 + within * 4);                             \
        }                                                                        \
        cp_commit();                                                             \
    }

    ISSUE_CHUNK(0, 0)
    ISSUE_CHUNK(1, 1)

    // ---- stage x: sxe[i][mm] = xp[mm], sxo[i][mm] = xp[mm+1]
    // xp[a] = (a in [1,14]) ? x[o*256+i][n][(a+12)%14] : 0
    {
        const float* xbase = x + ((size_t)o * 256) * 196 + n * 14;
#pragma unroll
        for (int rep = 0; rep < 8; rep++) {
            const int idx = rep * 512 + tid;       // 0..4095
            const int i = idx >> 4;
            const int mm = idx & 15;
            float ve = 0.f, vo = 0.f;
            if (mm >= 1 && mm <= 14) ve = xbase[(size_t)i * 196 + (mm + 12) % 14];
            if (mm + 1 <= 14)        vo = xbase[(size_t)i * 196 + (mm + 13) % 14];
            smem[SXE_OFF + idx] = ve;
            smem[SXO_OFF + idx] = vo;
        }
    }

    uint64_t A[7];
#pragma unroll
    for (int p = 0; p < 7; p++) A[p] = 0ull;

    // ---- main loop: 8 chunks, 3-deep pipeline, one barrier per chunk ----
#pragma unroll
    for (int c = 0; c < CHUNKS; c++) {
        if (c < CHUNKS - 1) cp_wait<1>(); else cp_wait<0>();   // chunk c landed
        __syncthreads();   // all warps past chunk c-1 (and x staging on c=0)
        if (c + 2 < CHUNKS) ISSUE_CHUNK(c + 2, (c + 2) % NBUF)

        const float* swp = smem + (c % NBUF) * CHUNK_FLOATS + (g * 4) * 192 + tx * 3;
        const float* xe  = smem + SXE_OFF + (size_t)(g * 32 + c * 4) * 16;
        const float* xo  = smem + SXO_OFF + (size_t)(g * 32 + c * 4) * 16;

#pragma unroll
        for (int il = 0; il < 4; il++) {
            const uint64_t W0 = pk2(swp[il * 192 + 0]);
            const uint64_t W1 = pk2(swp[il * 192 + 1]);
            const uint64_t W2 = pk2(swp[il * 192 + 2]);

            const ulonglong2 e01 = *(const ulonglong2*)(xe + il * 16);
            const ulonglong2 e23 = *(const ulonglong2*)(xe + il * 16 + 4);
            const ulonglong2 e45 = *(const ulonglong2*)(xe + il * 16 + 8);
            const ulonglong2 e67 = *(const ulonglong2*)(xe + il * 16 + 12);
            const ulonglong2 o01 = *(const ulonglong2*)(xo + il * 16);
            const ulonglong2 o23 = *(const ulonglong2*)(xo + il * 16 + 4);
            const ulonglong2 o45 = *(const ulonglong2*)(xo + il * 16 + 8);
            const uint64_t   o6  = *(const uint64_t*)  (xo + il * 16 + 12);

            uint64_t E[8] = {e01.x, e01.y, e23.x, e23.y, e45.x, e45.y, e67.x, e67.y};
            uint64_t O[7] = {o01.x, o01.y, o23.x, o23.y, o45.x, o45.y, o6};

#pragma unroll
            for (int p = 0; p < 7; p++) {
                A[p] = ffma2(W0, E[p],     A[p]);
                A[p] = ffma2(W1, O[p],     A[p]);
                A[p] = ffma2(W2, E[p + 1], A[p]);
            }
        }
    }

    // ---- cross-group reduction in smem ----
    __syncthreads();                     // all warps done with chunk-7 buffer
    uint64_t* ps = (uint64_t*)smem;      // ps[g*448 + tx*7 + p], 28KB
#pragma unroll
    for (int p = 0; p < 7; p++)
        ps[(size_t)g * 448 + tx * 7 + p] = A[p];
    __syncthreads();

    if (tid < 448) {
        const int k = tid / 7;           // 0..63
        const int p = tid % 7;
        float vlo = 0.f, vhi = 0.f;
#pragma unroll
        for (int gg = 0; gg < 8; gg++) { // fixed order -> deterministic
            const float2 v = ((const float2*)ps)[gg * 448 + k * 7 + p];
            vlo += v.x;
            vhi += v.y;
        }
        const int cg = o * 256 + kq * 64 + k;
        float2 s; s.x = vlo; s.y = vhi;
        *(float2*)&out[(size_t)cg * 196 + h * 14 + 2 * p] = s;
    }
}

extern "C" void kernel_launch(void* const* d_in, const int* in_sizes, int n_in,
                              void* d_out, int out_size) {
    const float* x = (const float*)d_in[0];   // (1,512,14,14)
    const float* w = (const float*)d_in[1];   // (256,256,3)
    float* out = (float*)d_out;

    cudaFuncSetAttribute(fused_conv_kernel,
                         cudaFuncAttributeMaxDynamicSharedMemorySize, SMEM_BYTES);
    fused_conv_kernel<<<112, 512, SMEM_BYTES>>>(x, w, out);
}